// round 3
// baseline (speedup 1.0000x reference)
#include <cuda_runtime.h>
#include <cstdint>

#define HDIM  1024
#define BATCH 2048
#define SEQL  96
#define VOCAB 96
#define NBH   (BATCH * HDIM)

// -------- device scratch (allocation-free rule: __device__ globals) --------
__device__ float g_h0[2][NBH];            // double-buffered layer-0 state
__device__ float g_hs[SEQL][NBH];         // all layer-1 states (FC input + recurrence)
__device__ float g_logits[(size_t)SEQL * BATCH * VOCAB];
__device__ float g_bias0[HDIM];
__device__ float g_bias1[HDIM];

typedef unsigned long long u64;

__device__ __forceinline__ void fma2(u64& d, u64 a, u64 b) {
    asm("fma.rn.f32x2 %0, %1, %2, %0;" : "+l"(d) : "l"(a), "l"(b));
}
__device__ __forceinline__ float pk_lo(u64 v) { return __uint_as_float((unsigned)(v & 0xffffffffull)); }
__device__ __forceinline__ float pk_hi(u64 v) { return __uint_as_float((unsigned)(v >> 32)); }

// ---------------------------------------------------------------------------
// prep: fuse biases, zero initial h0
// ---------------------------------------------------------------------------
__global__ void prep_kernel(const float* __restrict__ b0a, const float* __restrict__ b0b,
                            const float* __restrict__ b1a, const float* __restrict__ b1b) {
    int i = blockIdx.x * blockDim.x + threadIdx.x;
    if (i < HDIM) {
        g_bias0[i] = b0a[i] + b0b[i];
        g_bias1[i] = b1a[i] + b1b[i];
    }
    int stride = gridDim.x * blockDim.x;
    for (int j = i; j < NBH; j += stride) g_h0[0][j] = 0.0f;
}

// ---------------------------------------------------------------------------
// Fused GEMM + tanh:
//   C[m,n] = tanh( sum_k A0[m,k]*W0[n,k]  (+ sum_k A1[m,k]*W1[n,k] if DUAL)
//                  (+ x[m*SEQL+t]*wcol[n] if HAS_X)  + bias[n] )
// M=2048, N=1024, K=1024 (x2 if DUAL). 128x128 tile, 256 threads, 8x8 micro.
// K packed into even/odd pairs -> fma.rn.f32x2 (2x fp32 FMA rate on sm_103a).
// ---------------------------------------------------------------------------
template<bool HAS_X, bool DUAL>
__global__ void __launch_bounds__(256, 1)
gemm_tanh_kernel(const float* __restrict__ A0, const float* __restrict__ W0,
                 const float* __restrict__ A1, const float* __restrict__ W1,
                 float* __restrict__ C,
                 const float* __restrict__ x, const float* __restrict__ wcol,
                 const float* __restrict__ bias, int t)
{
    __shared__ __align__(16) float2 As[4][128];   // [k-pair][m]
    __shared__ __align__(16) float2 Bs[4][128];   // [k-pair][n]

    const int tid  = threadIdx.x;
    const int m0   = blockIdx.y << 7;
    const int n0   = blockIdx.x << 7;
    const int tx   = tid & 15;
    const int ty   = tid >> 4;
    const int lrow = tid >> 1;        // 0..127
    const int lcol = (tid & 1) << 2;  // 0 or 4
    const int kp0  = lcol >> 1;       // 0 or 2

    u64 acc[8][8];
    #pragma unroll
    for (int i = 0; i < 8; ++i)
        #pragma unroll
        for (int j = 0; j < 8; ++j) acc[i][j] = 0ull;

    const int npass = DUAL ? 2 : 1;
    for (int pass = 0; pass < npass; ++pass) {
        const float* A  = (pass == 0) ? A0 : A1;
        const float* W  = (pass == 0) ? W0 : W1;
        const float* Ap = A + (size_t)(m0 + lrow) * HDIM + lcol;
        const float* Wp = W + (size_t)(n0 + lrow) * HDIM + lcol;

        for (int kt = 0; kt < HDIM; kt += 8) {
            float4 av = __ldg((const float4*)(Ap + kt));
            float4 bv = __ldg((const float4*)(Wp + kt));
            __syncthreads();
            As[kp0    ][lrow] = make_float2(av.x, av.y);
            As[kp0 + 1][lrow] = make_float2(av.z, av.w);
            Bs[kp0    ][lrow] = make_float2(bv.x, bv.y);
            Bs[kp0 + 1][lrow] = make_float2(bv.z, bv.w);
            __syncthreads();

            #pragma unroll
            for (int kp = 0; kp < 4; ++kp) {
                u64 a2[8], b2[8];
                {
                    ulonglong2 p0 = *(const ulonglong2*)&As[kp][ty * 4];
                    ulonglong2 p1 = *(const ulonglong2*)&As[kp][ty * 4 + 2];
                    ulonglong2 p2 = *(const ulonglong2*)&As[kp][64 + ty * 4];
                    ulonglong2 p3 = *(const ulonglong2*)&As[kp][64 + ty * 4 + 2];
                    a2[0] = p0.x; a2[1] = p0.y; a2[2] = p1.x; a2[3] = p1.y;
                    a2[4] = p2.x; a2[5] = p2.y; a2[6] = p3.x; a2[7] = p3.y;
                }
                {
                    ulonglong2 q0 = *(const ulonglong2*)&Bs[kp][tx * 4];
                    ulonglong2 q1 = *(const ulonglong2*)&Bs[kp][tx * 4 + 2];
                    ulonglong2 q2 = *(const ulonglong2*)&Bs[kp][64 + tx * 4];
                    ulonglong2 q3 = *(const ulonglong2*)&Bs[kp][64 + tx * 4 + 2];
                    b2[0] = q0.x; b2[1] = q0.y; b2[2] = q1.x; b2[3] = q1.y;
                    b2[4] = q2.x; b2[5] = q2.y; b2[6] = q3.x; b2[7] = q3.y;
                }
                #pragma unroll
                for (int i = 0; i < 8; ++i)
                    #pragma unroll
                    for (int j = 0; j < 8; ++j)
                        fma2(acc[i][j], a2[i], b2[j]);
            }
        }
    }

    // Epilogue: reduce packed lanes, add bias (+ x outer term), tanh, store.
    #pragma unroll
    for (int i = 0; i < 8; ++i) {
        int row = m0 + ((i < 4) ? (ty * 4 + i) : (64 + ty * 4 + (i - 4)));
        float xv = 0.0f;
        if (HAS_X) xv = __ldg(&x[(size_t)row * SEQL + t]);
        #pragma unroll
        for (int j = 0; j < 8; ++j) {
            int col = n0 + ((j < 4) ? (tx * 4 + j) : (64 + tx * 4 + (j - 4)));
            float s = pk_lo(acc[i][j]) + pk_hi(acc[i][j]) + bias[col];
            if (HAS_X) s += xv * wcol[col];
            C[(size_t)row * HDIM + col] = tanhf(s);
        }
    }
}

// ---------------------------------------------------------------------------
// FC head: logits[r, v] = g_hs_flat[r, :] . fc_W[v, :] + fc_b[v]
// r = t*BATCH + b  (L*B = 196608 rows). Block = (96, 8): 8 rows, 1 v/thread.
// ---------------------------------------------------------------------------
__global__ void __launch_bounds__(768)
fc_kernel(const float* __restrict__ fcW, const float* __restrict__ fcb)
{
    __shared__ float hrow[8][HDIM];
    const float* hbase = &g_hs[0][0];
    int r0  = blockIdx.x * 8;
    int tid = threadIdx.y * 96 + threadIdx.x;

    for (int i = tid; i < 8 * HDIM; i += 768) {
        int rr = i >> 10, kk = i & 1023;
        hrow[rr][kk] = hbase[(size_t)(r0 + rr) * HDIM + kk];
    }
    __syncthreads();

    int v = threadIdx.x, ry = threadIdx.y;
    const float* w = fcW + (size_t)v * HDIM;
    float acc = 0.0f;
    #pragma unroll 4
    for (int k = 0; k < HDIM; k += 4) {
        float4 wv = __ldg((const float4*)(w + k));
        acc = fmaf(hrow[ry][k],     wv.x, acc);
        acc = fmaf(hrow[ry][k + 1], wv.y, acc);
        acc = fmaf(hrow[ry][k + 2], wv.z, acc);
        acc = fmaf(hrow[ry][k + 3], wv.w, acc);
    }
    g_logits[(size_t)(r0 + ry) * VOCAB + v] = acc + __ldg(&fcb[v]);
}

// ---------------------------------------------------------------------------
// Sequential probability patch. One warp per batch element, 96 steps.
// argmax ties break to lowest index (matches jnp.argmax).
// ---------------------------------------------------------------------------
__device__ __forceinline__ int warp_argmax3(float v0, float v1, float v2, int lane) {
    float mv = v0; int mi = lane;
    if (v1 > mv) { mv = v1; mi = lane + 32; }
    if (v2 > mv) { mv = v2; mi = lane + 64; }
    #pragma unroll
    for (int off = 16; off; off >>= 1) {
        float ov = __shfl_xor_sync(0xffffffffu, mv, off);
        int   oi = __shfl_xor_sync(0xffffffffu, mi, off);
        if (ov > mv || (ov == mv && oi < mi)) { mv = ov; mi = oi; }
    }
    return mi;
}

__global__ void adjust_kernel(float* __restrict__ out) {
    int gw   = (blockIdx.x * blockDim.x + threadIdx.x) >> 5;
    int lane = threadIdx.x & 31;
    if (gw >= BATCH) return;
    int b = gw;
    int prevarg = 0;

    for (int t = 0; t < SEQL; ++t) {
        const float* row = g_logits + ((size_t)t * BATCH + b) * VOCAB;
        float v0 = row[lane], v1 = row[lane + 32], v2 = row[lane + 64];

        int curarg = warp_argmax3(v0, v1, v2, lane);   // argmax of RAW row
        if (t > 0) {
            if (prevarg == 0 && curarg != 1 && lane == 1) v0 += 0.5f;           // U_IDX
            if (t == SEQL - 1 && curarg == 0 && lane == 0) v0 -= 0.5f;          // Q_IDX
        }
        float* o = out + ((size_t)b * SEQL + t) * VOCAB;
        o[lane] = v0; o[lane + 32] = v1; o[lane + 64] = v2;

        prevarg = warp_argmax3(v0, v1, v2, lane);      // argmax of ADJUSTED row
    }
}

// ---------------------------------------------------------------------------
// Final hidden states: out2 = [h0_final, h1_final], each [B, H]
// ---------------------------------------------------------------------------
__global__ void copy_hidden_kernel(float* __restrict__ out2) {
    int i = blockIdx.x * blockDim.x + threadIdx.x;
    if (i < NBH) {
        out2[i]       = g_h0[0][i];           // after 96 steps final h0 is buffer 0
        out2[NBH + i] = g_hs[SEQL - 1][i];
    }
}

// ---------------------------------------------------------------------------
extern "C" void kernel_launch(void* const* d_in, const int* in_sizes, int n_in,
                              void* d_out, int out_size)
{
    const float* x       = (const float*)d_in[0];
    const float* l0_Wih  = (const float*)d_in[1];   // (H, 1)
    const float* l0_Whh  = (const float*)d_in[2];   // (H, H)
    const float* l0_bih  = (const float*)d_in[3];
    const float* l0_bhh  = (const float*)d_in[4];
    const float* l1_Wih  = (const float*)d_in[5];
    const float* l1_Whh  = (const float*)d_in[6];
    const float* l1_bih  = (const float*)d_in[7];
    const float* l1_bhh  = (const float*)d_in[8];
    const float* fc_W    = (const float*)d_in[9];
    const float* fc_b    = (const float*)d_in[10];

    void* p;
    cudaGetSymbolAddress(&p, g_h0);    float* h0b = (float*)p;
    cudaGetSymbolAddress(&p, g_hs);    float* hsb = (float*)p;
    cudaGetSymbolAddress(&p, g_bias0); float* bias0 = (float*)p;
    cudaGetSymbolAddress(&p, g_bias1); float* bias1 = (float*)p;

    prep_kernel<<<1024, 256>>>(l0_bih, l0_bhh, l1_bih, l1_bhh);

    dim3 ggrid(HDIM / 128, BATCH / 128);   // (8, 16)
    for (int t = 0; t < SEQL; ++t) {
        float* h0_cur = h0b + (size_t)(t & 1) * NBH;
        float* h0_nxt = h0b + (size_t)((t & 1) ^ 1) * NBH;
        // layer 0: h0' = tanh(x_t * Wih0 + h0 @ Whh0^T + bias0)
        gemm_tanh_kernel<true, false><<<ggrid, 256>>>(
            h0_cur, l0_Whh, nullptr, nullptr, h0_nxt, x, l0_Wih, bias0, t);
        // layer 1: h1' = tanh(h0' @ Wih1^T + h1 @ Whh1^T + bias1)
        float* h1_out = hsb + (size_t)t * NBH;
        if (t == 0) {
            gemm_tanh_kernel<false, false><<<ggrid, 256>>>(
                h0_nxt, l1_Wih, nullptr, nullptr, h1_out, nullptr, nullptr, bias1, 0);
        } else {
            float* h1_prev = hsb + (size_t)(t - 1) * NBH;
            gemm_tanh_kernel<false, true><<<ggrid, 256>>>(
                h0_nxt, l1_Wih, h1_prev, l1_Whh, h1_out, nullptr, nullptr, bias1, 0);
        }
    }

    fc_kernel<<<(SEQL * BATCH) / 8, dim3(96, 8)>>>(fc_W, fc_b);

    float* out = (float*)d_out;
    adjust_kernel<<<BATCH / 8, 256>>>(out);
    copy_hidden_kernel<<<(NBH + 255) / 256, 256>>>(out + (size_t)BATCH * SEQL * VOCAB);
}